// round 1
// baseline (speedup 1.0000x reference)
#include <cuda_runtime.h>

#define BH   16
#define LQ   512
#define LK   512
#define DD   64
#define TQ   32
#define TK   128

// Scratch for the projected tensors (device globals: no allocation).
// g_Wq: [bh][q][d]   (d contiguous  -> float4 loads over d)
// g_Wk: [bh][d][k]   (k contiguous  -> conflict-free float4 loads over k)
__device__ float g_Wq[BH * LQ * DD];
__device__ float g_Wk[BH * DD * LK];

__device__ __forceinline__ float tanh_fast(float x) {
    float y;
    asm("tanh.approx.f32 %0, %1;" : "=f"(y) : "f"(x));
    return y;
}

// ---------------------------------------------------------------------------
// Projection Q: g_Wq[row][e] = sum_d Q[row][d] * W1[d][e] + b1[e]
// 256 threads: 4 rows x 64 e per block.
// ---------------------------------------------------------------------------
__global__ __launch_bounds__(256) void proj_q_kernel(
    const float* __restrict__ Q, const float* __restrict__ W1,
    const float* __restrict__ b1)
{
    __shared__ float Qs[4][DD];
    const int rowBase = blockIdx.x * 4;           // in [0, BH*LQ)
    const int tid = threadIdx.x;

    // load 4 rows of Q (4*64 = 256 floats, one per thread, coalesced)
    Qs[tid >> 6][tid & 63] = Q[(rowBase + (tid >> 6)) * DD + (tid & 63)];
    __syncthreads();

    const int ql = tid >> 6;
    const int e  = tid & 63;
    float acc = b1[e];
#pragma unroll
    for (int d = 0; d < DD; d++)
        acc += Qs[ql][d] * W1[d * DD + e];        // W1 coalesced over e, broadcast Qs
    g_Wq[(rowBase + ql) * DD + e] = acc;          // coalesced
}

// ---------------------------------------------------------------------------
// Projection K (output TRANSPOSED): g_Wk[bh][e][k] = sum_d K[bh][k][d]*W2[d][e] + b2[e]
// Block: 32 k-rows of one bh; 256 threads = 32 k x 8 e-groups; 8 e's per thread.
// ---------------------------------------------------------------------------
__global__ __launch_bounds__(256) void proj_k_kernel(
    const float* __restrict__ K, const float* __restrict__ W2,
    const float* __restrict__ b2)
{
    __shared__ float Ks[32][DD + 1];              // +1 pad: kills 32-way LDS conflict
    const int bh    = blockIdx.y;
    const int kBase = blockIdx.x * 32;
    const int tid   = threadIdx.x;

    for (int i = tid; i < 32 * DD; i += 256) {
        int r = i >> 6, d = i & 63;
        Ks[r][d] = K[((bh * LK) + kBase + r) * DD + d];
    }
    __syncthreads();

    const int kl = tid & 31;                      // k lane
    const int ey = tid >> 5;                      // e group (0..7)
    float acc[8];
#pragma unroll
    for (int n = 0; n < 8; n++) acc[n] = b2[ey * 8 + n];
#pragma unroll
    for (int d = 0; d < DD; d++) {
        const float kv = Ks[kl][d];               // padded: conflict-free
#pragma unroll
        for (int n = 0; n < 8; n++)
            acc[n] += kv * W2[d * DD + ey * 8 + n];  // broadcast within warp
    }
#pragma unroll
    for (int n = 0; n < 8; n++)
        g_Wk[(bh * DD + ey * 8 + n) * LK + kBase + kl] = acc[n];  // coalesced over k
}

// ---------------------------------------------------------------------------
// Main kernel: scores[bh][q][k] = sum_d tanh(wq[q][d] + wk[k][d]) * v[d] + bV
// Block = 256 threads, tile 32q x 128k, micro-tile 4x4 per thread.
// MUFU-bound by design: per element exactly 1 tanh.approx + 1 FADD + 1 FFMA.
// ---------------------------------------------------------------------------
__global__ __launch_bounds__(256) void attn_main_kernel(
    const float* __restrict__ Vv, const float* __restrict__ bV,
    float* __restrict__ out)
{
    __shared__ float wq_s[TQ][DD];    // 8 KB, reads are warp-broadcast
    __shared__ float wk_s[DD][TK];    // 32 KB, [d][k]: LDS.128 over k conflict-free
    __shared__ float v_s[DD];

    const int bh    = blockIdx.z;
    const int qBase = blockIdx.y * TQ;
    const int kBase = blockIdx.x * TK;
    const int tid   = threadIdx.x;

    // --- fill smem (all coalesced float4 copies) ---
    {
        const float4* src = (const float4*)(g_Wq + (bh * LQ + qBase) * DD);
        float4* dst = (float4*)&wq_s[0][0];
        for (int i = tid; i < TQ * DD / 4; i += 256) dst[i] = src[i];
    }
    for (int i = tid; i < DD * TK / 4; i += 256) {
        int d = i / (TK / 4), c = i % (TK / 4);
        ((float4*)&wk_s[d][0])[c] =
            ((const float4*)(g_Wk + (bh * DD + d) * LK + kBase))[c];
    }
    if (tid < DD) v_s[tid] = Vv[tid];
    __syncthreads();

    const int ty = tid >> 5;          // q group (warp id): all lanes same q rows
    const int tx = tid & 31;          // k lane

    float acc[4][4];
#pragma unroll
    for (int i = 0; i < 4; i++)
#pragma unroll
        for (int j = 0; j < 4; j++) acc[i][j] = 0.0f;

#pragma unroll 4
    for (int d = 0; d < DD; d += 4) {
        float4 wq4[4];
#pragma unroll
        for (int i = 0; i < 4; i++)
            wq4[i] = *(const float4*)&wq_s[ty * 4 + i][d];   // broadcast
        float4 wk4[4];
#pragma unroll
        for (int dd = 0; dd < 4; dd++)
            wk4[dd] = *(const float4*)&wk_s[d + dd][tx * 4]; // conflict-free
        const float4 v4 = *(const float4*)&v_s[d];

#pragma unroll
        for (int dd = 0; dd < 4; dd++) {
            const float vd  = (dd == 0) ? v4.x : (dd == 1) ? v4.y : (dd == 2) ? v4.z : v4.w;
            float wkv[4];
            wkv[0] = wk4[dd].x; wkv[1] = wk4[dd].y; wkv[2] = wk4[dd].z; wkv[3] = wk4[dd].w;
#pragma unroll
            for (int i = 0; i < 4; i++) {
                const float wqv = (dd == 0) ? wq4[i].x : (dd == 1) ? wq4[i].y
                                : (dd == 2) ? wq4[i].z : wq4[i].w;
#pragma unroll
                for (int j = 0; j < 4; j++)
                    acc[i][j] += tanh_fast(wqv + wkv[j]) * vd;
            }
        }
    }

    const float bv = bV[0];
#pragma unroll
    for (int i = 0; i < 4; i++) {
        float4 o;
        o.x = acc[i][0] + bv; o.y = acc[i][1] + bv;
        o.z = acc[i][2] + bv; o.w = acc[i][3] + bv;
        *(float4*)&out[((size_t)(bh * LQ + qBase + ty * 4 + i)) * LK + kBase + tx * 4] = o;
    }
}

// ---------------------------------------------------------------------------
// Launch
// ---------------------------------------------------------------------------
extern "C" void kernel_launch(void* const* d_in, const int* in_sizes, int n_in,
                              void* d_out, int out_size)
{
    const float* Q  = (const float*)d_in[0];
    const float* K  = (const float*)d_in[1];
    const float* W1 = (const float*)d_in[2];
    const float* b1 = (const float*)d_in[3];
    const float* W2 = (const float*)d_in[4];
    const float* b2 = (const float*)d_in[5];
    const float* V  = (const float*)d_in[6];
    const float* bV = (const float*)d_in[7];
    float* out = (float*)d_out;

    // Projections
    proj_q_kernel<<<BH * LQ / 4, 256>>>(Q, W1, b1);
    proj_k_kernel<<<dim3(LK / 32, BH), 256>>>(K, W2, b2);

    // Main scores kernel: grid 4 x 16 x 16 = 1024 blocks
    dim3 grid(LK / TK, LQ / TQ, BH);
    attn_main_kernel<<<grid, 256>>>(V, bV, out);
}

// round 2
// speedup vs baseline: 1.1180x; 1.1180x over previous
#include <cuda_runtime.h>

#define BH   16
#define LQ   512
#define LK   512
#define DD   64
#define TQ   32
#define TK   128

// Scratch for the projected tensors (device globals: no allocation).
// g_Wq: [bh][q][d]   (d contiguous  -> float4 loads over d)
// g_Wk: [bh][d][k]   (k contiguous  -> conflict-free float4 loads over k)
__device__ float g_Wq[BH * LQ * DD];
__device__ float g_Wk[BH * DD * LK];

__device__ __forceinline__ float tanh_fast(float x) {
    float y;
    asm("tanh.approx.f32 %0, %1;" : "=f"(y) : "f"(x));
    return y;
}

// ---------------------------------------------------------------------------
// Fused projection kernel.
//   blocks [0,256):    Q-projection  g_Wq[row][e] = Q[row]·W1[:,e] + b1[e]
//   blocks [256,512):  K-projection  g_Wk[bh][e][k] = K[bh,k]·W2[:,e] + b2[e]
// Each block: 32 rows. W (64x64, 16KB) and X rows (32x(64+1), 8.3KB) in smem.
// Thread = (lane=row, eg=e-group of 8). Per d: 1 LDS(x, conflict-free via pad)
// + 2 broadcast LDS.128(W) + 8 FFMA  ->  FMA-pipe bound.
// Q path stores through an smem transpose (reusing Xs) to keep STG coalesced;
// K path stores are naturally coalesced (lanes = k).
// ---------------------------------------------------------------------------
__global__ __launch_bounds__(256) void proj_fused_kernel(
    const float* __restrict__ Q, const float* __restrict__ K,
    const float* __restrict__ W1, const float* __restrict__ b1,
    const float* __restrict__ W2, const float* __restrict__ b2)
{
    __shared__ float Ws[DD][DD];       // 16 KB, [d][e] row-major like W
    __shared__ float Xs[32][DD + 1];   // 8.3 KB, padded: conflict-free column reads

    const int  tid  = threadIdx.x;
    const bool isK  = (blockIdx.x >= 256);
    const int  blk  = isK ? (blockIdx.x - 256) : blockIdx.x;
    const int  rowBase = blk * 32;     // global row in [0, BH*512)

    const float* __restrict__ X  = isK ? K  : Q;
    const float* __restrict__ W  = isK ? W2 : W1;
    const float* __restrict__ bb = isK ? b2 : b1;

    // Fill W smem: 4096 floats = 1024 float4, coalesced.
    {
        const float4* src = (const float4*)W;
        float4* dst = (float4*)&Ws[0][0];
#pragma unroll
        for (int t = 0; t < 4; t++) dst[tid + t * 256] = src[tid + t * 256];
    }
    // Fill X rows: 2048 floats, coalesced global reads, padded smem stores.
#pragma unroll
    for (int t = 0; t < 8; t++) {
        int i = tid + t * 256;
        int r = i >> 6, c = i & 63;
        Xs[r][c] = X[(size_t)(rowBase + r) * DD + c];
    }
    __syncthreads();

    const int lane = tid & 31;   // row within 32-row tile
    const int eg   = tid >> 5;   // e-group: e = eg*8 + j

    float acc[8];
#pragma unroll
    for (int j = 0; j < 8; j++) acc[j] = __ldg(&bb[eg * 8 + j]);

#pragma unroll
    for (int d = 0; d < DD; d++) {
        const float xv = Xs[lane][d];                       // conflict-free (pad 65)
        const float4 w0 = *(const float4*)&Ws[d][eg * 8];    // warp-broadcast
        const float4 w1 = *(const float4*)&Ws[d][eg * 8 + 4];
        acc[0] += xv * w0.x; acc[1] += xv * w0.y;
        acc[2] += xv * w0.z; acc[3] += xv * w0.w;
        acc[4] += xv * w1.x; acc[5] += xv * w1.y;
        acc[6] += xv * w1.z; acc[7] += xv * w1.w;
    }

    if (isK) {
        // Transposed store: g_Wk[(bh*64 + e)*512 + k]; lanes = k -> coalesced.
        const int row = rowBase + lane;       // (bh, k)
        const int bh  = row >> 9;
        const int k   = row & 511;
#pragma unroll
        for (int j = 0; j < 8; j++)
            g_Wk[(size_t)(bh * DD + eg * 8 + j) * LK + k] = acc[j];
    } else {
        // Stage through smem so STGs are coalesced over e.
        __syncthreads();                       // Xs reuse
#pragma unroll
        for (int j = 0; j < 8; j++)
            Xs[lane][eg * 8 + j] = acc[j];     // lanes distinct rows: conflict-free
        __syncthreads();
#pragma unroll
        for (int t = 0; t < 8; t++) {
            int i = tid + t * 256;
            int r = i >> 6, c = i & 63;
            g_Wq[(size_t)(rowBase + r) * DD + c] = Xs[r][c];  // coalesced
        }
    }
}

// ---------------------------------------------------------------------------
// Main kernel: scores[bh][q][k] = sum_d tanh(wq[q][d] + wk[k][d]) * v[d] + bV
// Block = 256 threads, tile 32q x 128k, micro-tile 4x4 per thread.
// MUFU-bound by design: per element exactly 1 tanh.approx + 1 FADD + 1 FFMA.
// ---------------------------------------------------------------------------
__global__ __launch_bounds__(256) void attn_main_kernel(
    const float* __restrict__ Vv, const float* __restrict__ bV,
    float* __restrict__ out)
{
    __shared__ float wq_s[TQ][DD];    // 8 KB, reads are warp-broadcast
    __shared__ float wk_s[DD][TK];    // 32 KB, [d][k]: LDS.128 over k conflict-free
    __shared__ float v_s[DD];

    const int bh    = blockIdx.z;
    const int qBase = blockIdx.y * TQ;
    const int kBase = blockIdx.x * TK;
    const int tid   = threadIdx.x;

    // --- fill smem (all coalesced float4 copies) ---
    {
        const float4* src = (const float4*)(g_Wq + (bh * LQ + qBase) * DD);
        float4* dst = (float4*)&wq_s[0][0];
        for (int i = tid; i < TQ * DD / 4; i += 256) dst[i] = src[i];
    }
    for (int i = tid; i < DD * TK / 4; i += 256) {
        int d = i / (TK / 4), c = i % (TK / 4);
        ((float4*)&wk_s[d][0])[c] =
            ((const float4*)(g_Wk + (bh * DD + d) * LK + kBase))[c];
    }
    if (tid < DD) v_s[tid] = Vv[tid];
    __syncthreads();

    const int ty = tid >> 5;          // q group (warp id): all lanes same q rows
    const int tx = tid & 31;          // k lane

    float acc[4][4];
#pragma unroll
    for (int i = 0; i < 4; i++)
#pragma unroll
        for (int j = 0; j < 4; j++) acc[i][j] = 0.0f;

#pragma unroll 4
    for (int d = 0; d < DD; d += 4) {
        float4 wq4[4];
#pragma unroll
        for (int i = 0; i < 4; i++)
            wq4[i] = *(const float4*)&wq_s[ty * 4 + i][d];   // broadcast
        float4 wk4[4];
#pragma unroll
        for (int dd = 0; dd < 4; dd++)
            wk4[dd] = *(const float4*)&wk_s[d + dd][tx * 4]; // conflict-free
        const float4 v4 = *(const float4*)&v_s[d];

#pragma unroll
        for (int dd = 0; dd < 4; dd++) {
            const float vd  = (dd == 0) ? v4.x : (dd == 1) ? v4.y : (dd == 2) ? v4.z : v4.w;
            float wkv[4];
            wkv[0] = wk4[dd].x; wkv[1] = wk4[dd].y; wkv[2] = wk4[dd].z; wkv[3] = wk4[dd].w;
#pragma unroll
            for (int i = 0; i < 4; i++) {
                const float wqv = (dd == 0) ? wq4[i].x : (dd == 1) ? wq4[i].y
                                : (dd == 2) ? wq4[i].z : wq4[i].w;
#pragma unroll
                for (int j = 0; j < 4; j++)
                    acc[i][j] += tanh_fast(wqv + wkv[j]) * vd;
            }
        }
    }

    const float bv = bV[0];
#pragma unroll
    for (int i = 0; i < 4; i++) {
        float4 o;
        o.x = acc[i][0] + bv; o.y = acc[i][1] + bv;
        o.z = acc[i][2] + bv; o.w = acc[i][3] + bv;
        *(float4*)&out[((size_t)(bh * LQ + qBase + ty * 4 + i)) * LK + kBase + tx * 4] = o;
    }
}

// ---------------------------------------------------------------------------
// Launch
// ---------------------------------------------------------------------------
extern "C" void kernel_launch(void* const* d_in, const int* in_sizes, int n_in,
                              void* d_out, int out_size)
{
    const float* Q  = (const float*)d_in[0];
    const float* K  = (const float*)d_in[1];
    const float* W1 = (const float*)d_in[2];
    const float* b1 = (const float*)d_in[3];
    const float* W2 = (const float*)d_in[4];
    const float* b2 = (const float*)d_in[5];
    const float* V  = (const float*)d_in[6];
    const float* bV = (const float*)d_in[7];
    float* out = (float*)d_out;

    // Fused projections: blocks [0,256) -> Q, [256,512) -> K
    proj_fused_kernel<<<512, 256>>>(Q, K, W1, b1, W2, b2);

    // Main scores kernel: grid 4 x 16 x 16 = 1024 blocks
    dim3 grid(LK / TK, LQ / TQ, BH);
    attn_main_kernel<<<grid, 256>>>(V, bV, out);
}